// round 1
// baseline (speedup 1.0000x reference)
#include <cuda_runtime.h>
#include <stdint.h>

// Weisfeiler-Lehman graph kernel, hash-based reformulation.
// G=64 graphs, N=4096 nodes, D=16 neighbors, 4 WL iterations.
//
// K[g,h] = sum over label-bins of F[g,l]*F[h,l] is invariant to the bin ids,
// so the reference's global lexsort-rank id assignment is replaced by a
// salted multiset hash. Decomposition:
//   K = W W^T                         (iter-0 bins, exact tiny GEMM)
//     + diag(4 * sum_n w[g,n]^2)      (singleton bins from iters 1..4)
//     + exact corrections for any hash slot with >=2 instances incl. a
//       non-iter0 instance (kept labels / signature collisions), via chains.

typedef unsigned long long u64;
typedef unsigned int u32;

#define GG 64
#define NN 4096
#define DD 16
#define T_ITER 4
#define POOL (5 * GG * NN)          // 1,310,720 instances total
#define TBITS 21
#define TSIZE (1u << TBITS)         // 2,097,152 slots
#define TMASK (TSIZE - 1u)

// -------- device scratch (static, no allocation) --------
__device__ u64   d_key[TSIZE];      // 16 MB  hash-table keys (0 = empty)
__device__ int   d_head[TSIZE];     //  8 MB  per-slot chain head (0 = empty, stores idx+1)
__device__ int   d_next[POOL];      //  chain links
__device__ u32   d_meta[POOL];      //  g | (later<<8)
__device__ float d_wrec[POOL];      //  instance weight
__device__ u32   d_ctr;             //  pool counter
__device__ float d_diag[GG];        //  4 * sum w^2 per graph
__device__ float d_K[GG * GG];      //  unnormalized gram

__device__ __forceinline__ u64 fmix64(u64 k) {
    k ^= k >> 33; k *= 0xff51afd7ed558ccdULL;
    k ^= k >> 33; k *= 0xc4ceb9fe1a85ec53ULL;
    k ^= k >> 33; return k;
}

__device__ __forceinline__ void insertInst(u64 key, int g, float w, int later) {
    u32 slot = (u32)fmix64(key ^ 0xA5A5A5A5DEADBEEFULL) & TMASK;
    for (;;) {
        u64 prev = atomicCAS(&d_key[slot], 0ULL, key);
        if (prev == 0ULL || prev == key) break;
        slot = (slot + 1u) & TMASK;
    }
    u32 idx = atomicAdd(&d_ctr, 1u);
    d_meta[idx] = (u32)g | ((u32)later << 8);
    d_wrec[idx] = w;
    d_next[idx] = atomicExch(&d_head[slot], (int)(idx + 1u));
}

// -------- kernel 1: zero table state --------
__global__ void zeroK() {
    u32 i = blockIdx.x * blockDim.x + threadIdx.x;
    if (i < TSIZE) { d_key[i] = 0ULL; d_head[i] = 0; }
    if (i == 0) d_ctr = 0u;
}

// -------- kernel 2: WL iterations + instance inserts (one CTA per graph) --------
__global__ void __launch_bounds__(1024) wlK(const int* __restrict__ nbr,
                                            const float* __restrict__ nw) {
    const int g = blockIdx.x;
    const int tid = threadIdx.x;
    __shared__ u64 cur[NN];          // 32 KB: labels of this graph (fmix-space)

    float wsq = 0.f;
    for (int n = tid; n < NN; n += 1024) {
        u64 l0 = fmix64((u64)(n + 1)) | 1ULL;   // initial label, shared across graphs
        cur[n] = l0;
        float w = nw[g * NN + n];
        wsq += w * w;
        insertInst(l0, g, w, 0);
    }
    __syncthreads();

    for (int t = 1; t <= T_ITER; t++) {
        u64 newl[4];
        #pragma unroll
        for (int k = 0; k < 4; k++) {
            const int n = tid + k * 1024;
            const u64 own = cur[n];
            const int4* p = reinterpret_cast<const int4*>(nbr + ((size_t)g * NN + n) * DD);
            u64 s1 = 0, s2 = 0;
            bool keep = true;
            #pragma unroll
            for (int q = 0; q < 4; q++) {
                int4 v4 = p[q];
                int ids[4] = {v4.x, v4.y, v4.z, v4.w};
                #pragma unroll
                for (int j = 0; j < 4; j++) {
                    u64 v = cur[ids[j]];
                    keep = keep && (v == own);
                    s1 += v;
                    s2 += v * v;
                }
            }
            u64 h = fmix64(own + (u64)t * 0x9E3779B97F4A7C15ULL);
            h = fmix64(h ^ s1);
            h = fmix64(h + s2 * 0xC2B2AE3D27D4EB4FULL);
            h |= 1ULL;
            newl[k] = keep ? own : h;
        }
        __syncthreads();
        #pragma unroll
        for (int k = 0; k < 4; k++) cur[tid + k * 1024] = newl[k];
        __syncthreads();
        #pragma unroll
        for (int k = 0; k < 4; k++) {
            const int n = tid + k * 1024;
            insertInst(newl[k], g, nw[g * NN + n], 1);
        }
    }

    // diag term: 4 * sum_n w^2 (one instance per node per later-iteration)
    __shared__ float sred;
    if (tid == 0) sred = 0.f;
    __syncthreads();
    atomicAdd(&sred, wsq);
    __syncthreads();
    if (tid == 0) d_diag[g] = 4.0f * sred;
}

// -------- kernel 3: base gram  K = W W^T + diag --------
__global__ void gramK(const float* __restrict__ nw) {
    const int g = blockIdx.x;
    const int h = threadIdx.x;  // 64 threads
    __shared__ float sw[NN];
    for (int i = h; i < NN; i += 64) sw[i] = nw[g * NN + i];
    __syncthreads();
    const float4* rw  = reinterpret_cast<const float4*>(nw + (size_t)h * NN);
    const float4* sw4 = reinterpret_cast<const float4*>(sw);
    float acc = 0.f;
    #pragma unroll 4
    for (int i = 0; i < NN / 4; i++) {
        float4 a = sw4[i];
        float4 b = rw[i];
        acc += a.x * b.x + a.y * b.y + a.z * b.z + a.w * b.w;
    }
    if (g == h) acc += d_diag[g];
    d_K[g * GG + h] = acc;
}

// -------- kernel 4: exact corrections for multi-instance slots --------
__global__ void fixK() {
    u32 s = blockIdx.x * blockDim.x + threadIdx.x;
    if (s >= TSIZE) return;
    int hp = d_head[s];
    if (hp == 0) return;

    int total = 0, later = 0;
    for (int i = hp; i != 0; i = d_next[i - 1]) {
        total++;
        later += (int)((d_meta[i - 1] >> 8) & 1u);
    }
    if (later == 0 || total < 2) return;   // fully covered by GEMM / diag terms

    float f0[GG], f1[GG], s2g[GG];
    for (int g = 0; g < GG; g++) { f0[g] = 0.f; f1[g] = 0.f; s2g[g] = 0.f; }
    for (int i = hp; i != 0; i = d_next[i - 1]) {
        u32 m = d_meta[i - 1];
        float w = d_wrec[i - 1];
        int g = (int)(m & 0xFFu);
        if ((m >> 8) & 1u) { f1[g] += w; s2g[g] += w * w; }
        else               { f0[g] += w; }
    }
    for (int a = 0; a < GG; a++) {
        float fa = f0[a] + f1[a];
        if (fa == 0.f) continue;
        for (int b = 0; b < GG; b++) {
            float fb = f0[b] + f1[b];
            if (fb == 0.f) continue;
            float corr = fa * fb - f0[a] * f0[b];
            if (a == b) corr -= s2g[a];
            if (corr != 0.f) atomicAdd(&d_K[a * GG + b], corr);
        }
    }
}

// -------- kernel 5: normalize --------
__global__ void normK(float* __restrict__ out) {
    int i = blockIdx.x * blockDim.x + threadIdx.x;
    if (i >= GG * GG) return;
    int g = i >> 6, h = i & 63;
    float kg = d_K[g * GG + g];
    float kh = d_K[h * GG + h];
    out[i] = d_K[i] / (sqrtf(kg) * sqrtf(kh));
}

extern "C" void kernel_launch(void* const* d_in, const int* in_sizes, int n_in,
                              void* d_out, int out_size) {
    // metadata order: nbr [G*N*D] int32, node_weights [G*N] float32.
    // Defensive: identify by size.
    const int* nbr;
    const float* nw;
    if (in_sizes[0] == GG * NN * DD) {
        nbr = (const int*)d_in[0];
        nw  = (const float*)d_in[1];
    } else {
        nbr = (const int*)d_in[1];
        nw  = (const float*)d_in[0];
    }
    float* out = (float*)d_out;

    zeroK<<<TSIZE / 256, 256>>>();
    wlK<<<GG, 1024>>>(nbr, nw);
    gramK<<<GG, 64>>>(nw);
    fixK<<<TSIZE / 256, 256>>>();
    normK<<<(GG * GG + 255) / 256, 256>>>(out);
}

// round 2
// speedup vs baseline: 3.2673x; 3.2673x over previous
#include <cuda_runtime.h>
#include <stdint.h>

// WL graph kernel v2 — hash-based, full-chip clustered WL, atomic-minimal.
// G=64, N=4096, D=16, T=4.
//
// K = W W^T (+5x on diag)  [iter-0 bins + singleton later bins]
//   + exact corrections for any hash-table key with >=2 later instances,
//     or a kept iter-0 label (both self-report to a tiny overflow list).
//
// Labels are 64-bit keys. Multiset hash = 32-bit sum of neighbor label low
// words; new label = fmix64((own + t*SALT) ^ (sum * PHI64)). "keep" rule
// approximated by sum == 16*own_lo (exact when truly all-equal; false
// positive prob 2^-32 per node-iter).

typedef unsigned long long u64;
typedef unsigned int u32;

#define GG 64
#define NN 4096
#define DD 16
#define T_ITER 4
#define CLU 4
#define TPB 512
#define NPC (NN / CLU)            // 1024 nodes per CTA
#define TBITS 21
#define TSIZE (1u << TBITS)       // 2M slots
#define TMASK (TSIZE - 1u)
#define OVF_CAP 65536

// ---- static device scratch (no allocation) ----
__device__ u64   d_key[TSIZE];                // 16 MB hash table (0 = empty)
__device__ u64   d_lab[T_ITER * GG * NN];     //  8 MB labels (for rare fixup scan)
__device__ u64   d_ovf[OVF_CAP];              //  overflow: keys needing exact fixup
__device__ u32   d_ovf_cnt;
__device__ float d_K[GG * GG];

// ---- hashing ----
__device__ __forceinline__ u32 fmix32(u32 h) {
    h ^= h >> 16; h *= 0x85ebca6bu;
    h ^= h >> 13; h *= 0xc2b2ae35u;
    h ^= h >> 16; return h;
}
__device__ __forceinline__ u64 fmix64(u64 k) {
    k ^= k >> 33; k *= 0xff51afd7ed558ccdULL;
    k ^= k >> 33; k *= 0xc4ceb9fe1a85ec53ULL;
    k ^= k >> 33; return k;
}
// iter-0 key for node n: hi = (n+1)<<1 (recognizable), lo = mixed (bit0=0)
__device__ __forceinline__ u32 key0_lo(int n) { return fmix32((u32)n) & ~1u; }
__device__ __forceinline__ u32 key0_hi(int n) { return (u32)(n + 1) << 1; }

// ---- cluster helpers ----
__device__ __forceinline__ u32 smem_u32(const void* p) {
    return (u32)__cvta_generic_to_shared(p);
}
__device__ __forceinline__ u32 mapa_sh(u32 a, u32 r) {
    u32 o; asm("mapa.shared::cluster.u32 %0, %1, %2;" : "=r"(o) : "r"(a), "r"(r));
    return o;
}
__device__ __forceinline__ void st_sh_cluster(u32 a, u32 v) {
    asm volatile("st.shared::cluster.u32 [%0], %1;" :: "r"(a), "r"(v) : "memory");
}
__device__ __forceinline__ u32 ctarank() {
    u32 r; asm("mov.u32 %0, %%cluster_ctarank;" : "=r"(r)); return r;
}
__device__ __forceinline__ void cluster_sync_() {
    asm volatile("barrier.cluster.arrive.aligned;" ::: "memory");
    asm volatile("barrier.cluster.wait.aligned;" ::: "memory");
}

// ---- kernel 1: clear table + overflow counter ----
__global__ void zeroK() {
    u32 i = blockIdx.x * blockDim.x + threadIdx.x;
    if (i < TSIZE / 2) reinterpret_cast<ulonglong2*>(d_key)[i] = make_ulonglong2(0ULL, 0ULL);
    if (i == 0) d_ovf_cnt = 0u;
}

// ---- WL side effects: record label, self-report or table-insert ----
__device__ __forceinline__ void sideFx(u64 lab, int g, int t, int n) {
    d_lab[(((size_t)(t - 1) * GG + g) << 12) + n] = lab;
    u32 hi = (u32)(lab >> 32);
    u32 m = hi >> 1;
    if (!(hi & 1u) && (m - 1u) < (u32)NN && (u32)lab == key0_lo((int)(m - 1u))) {
        // kept iter-0 label: bin shared with 64 iter-0 ghosts -> self-report
        u32 id = atomicAdd(&d_ovf_cnt, 1u);
        if (id < OVF_CAP) d_ovf[id] = lab;
        return;
    }
    u32 slot = ((u32)lab >> 1) & TMASK;
    for (;;) {
        u64 prev = atomicCAS(reinterpret_cast<unsigned long long*>(&d_key[slot]),
                             0ULL, (unsigned long long)lab);
        if (prev == 0ULL) break;           // fresh, singleton so far
        if (prev == lab) {                 // duplicate bin -> self-report
            u32 id = atomicAdd(&d_ovf_cnt, 1u);
            if (id < OVF_CAP) d_ovf[id] = lab;
            break;
        }
        slot = (slot + 1u) & TMASK;
    }
}

// ---- kernel 2: 4 WL iterations; one 4-CTA cluster per graph ----
__global__ void __launch_bounds__(TPB, 2) __cluster_dims__(CLU, 1, 1)
wlK(const int* __restrict__ nbr) {
    __shared__ u32 lab_lo[NN];                 // full replicated copy (16 KB)
    const int tid = threadIdx.x;
    const u32 rank = ctarank();
    const int g = blockIdx.x / CLU;

    // every CTA fills its own full copy (identical data, no DSMEM needed)
    #pragma unroll
    for (int i = tid; i < NN; i += TPB) lab_lo[i] = key0_lo(i);

    const int n0 = (int)rank * NPC + tid;
    const int n1 = n0 + TPB;
    u32 lo0 = key0_lo(n0), hi0 = key0_hi(n0);
    u32 lo1 = key0_lo(n1), hi1 = key0_hi(n1);

    u32 myaddr = smem_u32(lab_lo);
    u32 paddr0 = mapa_sh(myaddr, 0), paddr1 = mapa_sh(myaddr, 1);
    u32 paddr2 = mapa_sh(myaddr, 2), paddr3 = mapa_sh(myaddr, 3);

    __syncthreads();   // local init complete before local reads

    const u64 PHI = 0x9E3779B97F4A7C15ULL;
    #pragma unroll 1
    for (int t = 1; t <= T_ITER; t++) {
        const u64 salt = (u64)t * 0xD6E8FEB86659FD93ULL;
        u64 lab[2];
        #pragma unroll
        for (int k = 0; k < 2; k++) {
            const int n = k ? n1 : n0;
            const u32 lo = k ? lo1 : lo0;
            const u32 hi = k ? hi1 : hi0;
            const int4* p = reinterpret_cast<const int4*>(nbr + ((size_t)g * NN + n) * DD);
            int4 a = p[0], b = p[1], c = p[2], d4 = p[3];
            u32 s = lab_lo[a.x] + lab_lo[a.y] + lab_lo[a.z] + lab_lo[a.w]
                  + lab_lo[b.x] + lab_lo[b.y] + lab_lo[b.z] + lab_lo[b.w]
                  + lab_lo[c.x] + lab_lo[c.y] + lab_lo[c.z] + lab_lo[c.w]
                  + lab_lo[d4.x] + lab_lo[d4.y] + lab_lo[d4.z] + lab_lo[d4.w];
            u64 own = ((u64)hi << 32) | lo;
            u64 h = fmix64((own + salt) ^ ((u64)s * PHI));
            u64 nk = (h | 2ULL) & ~1ULL;
            lab[k] = (s == lo * 16u) ? own : nk;
        }
        // side effects are smem-independent: overlap with the barrier
        sideFx(lab[0], g, t, n0);
        sideFx(lab[1], g, t, n1);

        cluster_sync_();   // all reads done cluster-wide
        u32 nl0 = (u32)lab[0], nl1 = (u32)lab[1];
        u32 off0 = (u32)n0 * 4u, off1 = (u32)n1 * 4u;
        st_sh_cluster(paddr0 + off0, nl0);  st_sh_cluster(paddr0 + off1, nl1);
        st_sh_cluster(paddr1 + off0, nl0);  st_sh_cluster(paddr1 + off1, nl1);
        st_sh_cluster(paddr2 + off0, nl0);  st_sh_cluster(paddr2 + off1, nl1);
        st_sh_cluster(paddr3 + off0, nl0);  st_sh_cluster(paddr3 + off1, nl1);
        lo0 = nl0; hi0 = (u32)(lab[0] >> 32);
        lo1 = nl1; hi1 = (u32)(lab[1] >> 32);
        cluster_sync_();   // writes visible cluster-wide
    }
}

// ---- kernel 3: K = W W^T, diag x5 (GEMM term + 4*sum(w^2) singleton term) ----
__global__ void __launch_bounds__(512) gramK(const float* __restrict__ nw) {
    __shared__ float sw[NN];
    const int g = blockIdx.x, tid = threadIdx.x;
    for (int i = tid; i < NN; i += 512) sw[i] = nw[(size_t)g * NN + i];
    __syncthreads();
    const int h = tid >> 3, part = tid & 7;
    const float4* rw = reinterpret_cast<const float4*>(nw + (size_t)h * NN);
    const float4* s4 = reinterpret_cast<const float4*>(sw);
    float acc = 0.f;
    #pragma unroll 4
    for (int i = part * 128; i < part * 128 + 128; i++) {
        float4 a = s4[i], b = rw[i];
        acc += a.x * b.x + a.y * b.y + a.z * b.z + a.w * b.w;
    }
    acc += __shfl_xor_sync(0xffffffffu, acc, 4);
    acc += __shfl_xor_sync(0xffffffffu, acc, 2);
    acc += __shfl_xor_sync(0xffffffffu, acc, 1);
    if (part == 0) {
        if (g == h) acc *= 5.0f;
        d_K[g * GG + h] = acc;
    }
}

// ---- kernel 4: exact correction for reported keys (expected empty) ----
__global__ void fixOvf(const float* __restrict__ nw) {
    u32 M = d_ovf_cnt; if (M > OVF_CAP) M = OVF_CAP;
    u32 i = blockIdx.x * blockDim.x + threadIdx.x;
    if (i >= M) return;
    u64 key = d_ovf[i];
    for (u32 j = 0; j < i; j++) if (d_ovf[j] == key) return;  // one leader per key

    float f1[GG]; float s2 = 0.f;
    for (int a = 0; a < GG; a++) f1[a] = 0.f;
    for (int idx = 0; idx < T_ITER * GG * NN; idx++) {
        if (d_lab[idx] == key) {
            int g = (idx >> 12) & (GG - 1);
            int n = idx & (NN - 1);
            float w = nw[(size_t)g * NN + n];
            f1[g] += w; s2 += w * w;
        }
    }
    bool i0 = false; int n0 = 0;
    u32 hi = (u32)(key >> 32), m = hi >> 1;
    if (!(hi & 1u) && (m - 1u) < (u32)NN && (u32)key == key0_lo((int)(m - 1u))) {
        i0 = true; n0 = (int)(m - 1u);
    }
    for (int a = 0; a < GG; a++) {
        float f0a = i0 ? nw[(size_t)a * NN + n0] : 0.f;
        float fa = f0a + f1[a];
        if (fa == 0.f && f0a == 0.f) continue;
        for (int b = 0; b < GG; b++) {
            float f0b = i0 ? nw[(size_t)b * NN + n0] : 0.f;
            float fb = f0b + f1[b];
            float corr = fa * fb - f0a * f0b;        // minus GEMM double count
            if (a == b) corr -= s2;                  // minus diag double count
            if (corr != 0.f) atomicAdd(&d_K[a * GG + b], corr);
        }
    }
}

// ---- kernel 5: normalize ----
__global__ void normK(float* __restrict__ out) {
    int i = blockIdx.x * blockDim.x + threadIdx.x;
    if (i >= GG * GG) return;
    int g = i >> 6, h = i & 63;
    out[i] = d_K[i] / sqrtf(d_K[g * GG + g] * d_K[h * GG + h]);
}

extern "C" void kernel_launch(void* const* d_in, const int* in_sizes, int n_in,
                              void* d_out, int out_size) {
    const int* nbr;
    const float* nw;
    if (in_sizes[0] == GG * NN * DD) {
        nbr = (const int*)d_in[0];
        nw  = (const float*)d_in[1];
    } else {
        nbr = (const int*)d_in[1];
        nw  = (const float*)d_in[0];
    }
    float* out = (float*)d_out;

    zeroK <<<(TSIZE / 2) / 256, 256>>> ();
    wlK   <<<GG * CLU, TPB>>> (nbr);
    gramK <<<GG, 512>>> (nw);
    fixOvf<<<OVF_CAP / 256, 256>>> (nw);
    normK <<<(GG * GG + 255) / 256, 256>>> (out);
}

// round 3
// speedup vs baseline: 3.3997x; 1.0405x over previous
#include <cuda_runtime.h>
#include <stdint.h>

// WL graph kernel v3 — nbr hoisted to registers, double-buffered labels
// (1 cluster.sync/iter), cheap bijective hash, 3 fused launches.
// G=64, N=4096, D=16, T=4.
//
// K = W W^T (diag x5)  [iter-0 bins + singleton later bins]
//   + exact corrections for any key with >=2 later instances or a kept
//     iter-0 label (self-reported via hash-table CAS to an overflow list,
//     fixed exactly in K3; expected empty for this data).

typedef unsigned long long u64;
typedef unsigned int u32;

#define GG 64
#define NN 4096
#define DD 16
#define T_ITER 4
#define CLU 4
#define TPB 512
#define NPC (NN / CLU)
#define TBITS 21
#define TSIZE (1u << TBITS)
#define TMASK (TSIZE - 1u)
#define OVF_CAP 4096

// ---- static device scratch ----
__device__ u64   d_key[TSIZE];               // 16 MB hash table (0 = empty)
__device__ u64   d_lab[T_ITER * GG * NN];    //  8 MB labels (fixup scan)
__device__ u64   d_ovf[OVF_CAP];
__device__ u32   d_ovf_cnt;
__device__ float d_K[GG * GG];

// ---- hashing ----
__device__ __forceinline__ u32 fmix32(u32 h) {
    h ^= h >> 16; h *= 0x85ebca6bu;
    h ^= h >> 13; h *= 0xc2b2ae35u;
    h ^= h >> 16; return h;
}
__device__ __forceinline__ u32 key0_lo(int n) { return fmix32((u32)n) & ~1u; }
__device__ __forceinline__ u32 key0_hi(int n) { return (u32)(n + 1) << 1; }

// ---- cluster helpers ----
__device__ __forceinline__ u32 smem_u32(const void* p) {
    return (u32)__cvta_generic_to_shared(p);
}
__device__ __forceinline__ u32 mapa_sh(u32 a, u32 r) {
    u32 o; asm("mapa.shared::cluster.u32 %0, %1, %2;" : "=r"(o) : "r"(a), "r"(r));
    return o;
}
__device__ __forceinline__ void st_sh_cluster(u32 a, u32 v) {
    asm volatile("st.shared::cluster.u32 [%0], %1;" :: "r"(a), "r"(v) : "memory");
}
__device__ __forceinline__ u32 ctarank() {
    u32 r; asm("mov.u32 %0, %%cluster_ctarank;" : "=r"(r)); return r;
}
__device__ __forceinline__ void cluster_sync_() {
    asm volatile("barrier.cluster.arrive.aligned;" ::: "memory");
    asm volatile("barrier.cluster.wait.aligned;" ::: "memory");
}

// ---- side effects: record label; self-report dups / kept iter-0 labels ----
__device__ __forceinline__ void sideFx(u64 lab, int g, int t, int n) {
    d_lab[(((size_t)(t - 1) * GG + g) << 12) + n] = lab;
    u32 hi = (u32)(lab >> 32);
    u32 m = hi >> 1;
    if (!(hi & 1u) && (m - 1u) < (u32)NN && (u32)lab == key0_lo((int)(m - 1u))) {
        u32 id = atomicAdd(&d_ovf_cnt, 1u);
        if (id < OVF_CAP) d_ovf[id] = lab;
        return;
    }
    u32 slot = ((u32)lab >> 1) & TMASK;
    for (;;) {
        u64 prev = atomicCAS(reinterpret_cast<unsigned long long*>(&d_key[slot]),
                             0ULL, (unsigned long long)lab);
        if (prev == 0ULL) break;
        if (prev == lab) {
            u32 id = atomicAdd(&d_ovf_cnt, 1u);
            if (id < OVF_CAP) d_ovf[id] = lab;
            break;
        }
        slot = (slot + 1u) & TMASK;
    }
}

// ---- K1: fused table-zero + gram (K = W W^T, diag x5) ----
__global__ void __launch_bounds__(512) prepK(const float* __restrict__ nw) {
    const int tid = threadIdx.x;
    if (blockIdx.x >= GG) {
        // zero blocks: 256 blocks cover 16 MB of d_key as ulonglong2
        const int zb = blockIdx.x - GG;
        ulonglong2* p = reinterpret_cast<ulonglong2*>(d_key);
        const int base = zb * (512 * 8);
        #pragma unroll
        for (int k = 0; k < 8; k++)
            p[base + k * 512 + tid] = make_ulonglong2(0ULL, 0ULL);
        if (zb == 0 && tid == 0) d_ovf_cnt = 0u;
        return;
    }
    __shared__ float sw[NN];
    const int g = blockIdx.x;
    for (int i = tid; i < NN; i += 512) sw[i] = nw[(size_t)g * NN + i];
    __syncthreads();
    const int h = tid >> 3, part = tid & 7;
    const float4* rw = reinterpret_cast<const float4*>(nw + (size_t)h * NN);
    const float4* s4 = reinterpret_cast<const float4*>(sw);
    float acc = 0.f;
    #pragma unroll 4
    for (int i = part * 128; i < part * 128 + 128; i++) {
        float4 a = s4[i], b = rw[i];
        acc += a.x * b.x + a.y * b.y + a.z * b.z + a.w * b.w;
    }
    acc += __shfl_xor_sync(0xffffffffu, acc, 4);
    acc += __shfl_xor_sync(0xffffffffu, acc, 2);
    acc += __shfl_xor_sync(0xffffffffu, acc, 1);
    if (part == 0) {
        if (g == h) acc *= 5.0f;
        d_K[g * GG + h] = acc;
    }
}

// ---- K2: 4 WL iterations; 4-CTA cluster per graph, 2 nodes/thread ----
__global__ void __launch_bounds__(TPB, 2) __cluster_dims__(CLU, 1, 1)
wlK(const int* __restrict__ nbr) {
    __shared__ u32 buf[2][NN];                  // double-buffered full copy, 32 KB
    const int tid = threadIdx.x;
    const u32 rank = ctarank();
    const int g = blockIdx.x / CLU;

    const int n0 = (int)rank * NPC + tid;
    const int n1 = n0 + TPB;

    // hoist neighbor lists into registers (iteration-invariant)
    const int4* p0 = reinterpret_cast<const int4*>(nbr + ((size_t)g * NN + n0) * DD);
    const int4* p1 = reinterpret_cast<const int4*>(nbr + ((size_t)g * NN + n1) * DD);
    int4 A0 = p0[0], A1 = p0[1], A2 = p0[2], A3 = p0[3];
    int4 B0 = p1[0], B1 = p1[1], B2 = p1[2], B3 = p1[3];

    // init buffer 0 (own full replicated copy)
    #pragma unroll
    for (int i = tid; i < NN; i += TPB) buf[0][i] = key0_lo(i);

    u32 lo0 = key0_lo(n0), hi0 = key0_hi(n0);
    u32 lo1 = key0_lo(n1), hi1 = key0_hi(n1);

    const u32 myaddr = smem_u32(&buf[0][0]);
    const u32 pa0 = mapa_sh(myaddr, 0), pa1 = mapa_sh(myaddr, 1);
    const u32 pa2 = mapa_sh(myaddr, 2), pa3 = mapa_sh(myaddr, 3);

    __syncthreads();
    cluster_sync_();   // all CTAs resident + buf[0] initialized everywhere

    const u64 PHI = 0x9E3779B97F4A7C15ULL;
    const u64 M1  = 0xff51afd7ed558ccdULL;
    #pragma unroll 1
    for (int t = 1; t <= T_ITER; t++) {
        const u32* cur = buf[(t - 1) & 1];
        const u32 nxtoff = (u32)((t & 1) * (NN * 4));
        const u64 salt = (u64)t * 0xD6E8FEB86659FD93ULL;

        u32 s0 = cur[A0.x] + cur[A0.y] + cur[A0.z] + cur[A0.w]
               + cur[A1.x] + cur[A1.y] + cur[A1.z] + cur[A1.w]
               + cur[A2.x] + cur[A2.y] + cur[A2.z] + cur[A2.w]
               + cur[A3.x] + cur[A3.y] + cur[A3.z] + cur[A3.w];
        u32 s1 = cur[B0.x] + cur[B0.y] + cur[B0.z] + cur[B0.w]
               + cur[B1.x] + cur[B1.y] + cur[B1.z] + cur[B1.w]
               + cur[B2.x] + cur[B2.y] + cur[B2.z] + cur[B2.w]
               + cur[B3.x] + cur[B3.y] + cur[B3.z] + cur[B3.w];

        u64 own0 = ((u64)hi0 << 32) | lo0;
        u64 own1 = ((u64)hi1 << 32) | lo1;
        u64 h0 = (own0 + salt + (u64)s0 * PHI) * M1;  h0 ^= h0 >> 32;
        u64 h1 = (own1 + salt + (u64)s1 * PHI) * M1;  h1 ^= h1 >> 32;
        u64 lab0 = (s0 == lo0 * 16u) ? own0 : ((h0 | 2ULL) & ~1ULL);
        u64 lab1 = (s1 == lo1 * 16u) ? own1 : ((h1 | 2ULL) & ~1ULL);

        // global side effects (off the smem critical path)
        sideFx(lab0, g, t, n0);
        sideFx(lab1, g, t, n1);

        // publish new labels to all 4 replicated copies (other buffer: no
        // pre-write sync needed)
        u32 nl0 = (u32)lab0, nl1 = (u32)lab1;
        u32 o0 = nxtoff + (u32)n0 * 4u, o1 = nxtoff + (u32)n1 * 4u;
        st_sh_cluster(pa0 + o0, nl0);  st_sh_cluster(pa0 + o1, nl1);
        st_sh_cluster(pa1 + o0, nl0);  st_sh_cluster(pa1 + o1, nl1);
        st_sh_cluster(pa2 + o0, nl0);  st_sh_cluster(pa2 + o1, nl1);
        st_sh_cluster(pa3 + o0, nl0);  st_sh_cluster(pa3 + o1, nl1);
        lo0 = nl0; hi0 = (u32)(lab0 >> 32);
        lo1 = nl1; hi1 = (u32)(lab1 >> 32);

        cluster_sync_();   // writes visible cluster-wide before next reads
    }
}

// ---- K3: single-block exact fixups (expected none) + normalize ----
__global__ void __launch_bounds__(1024) fixnormK(const float* __restrict__ nw,
                                                 float* __restrict__ out) {
    const int tid = threadIdx.x;
    __shared__ float f1[GG];
    __shared__ float s2sh;
    __shared__ int skip;

    u32 M = d_ovf_cnt; if (M > OVF_CAP) M = OVF_CAP;
    for (u32 i = 0; i < M; i++) {
        u64 key = d_ovf[i];
        if (tid == 0) {
            int sk = 0;
            for (u32 j = 0; j < i; j++) if (d_ovf[j] == key) { sk = 1; break; }
            skip = sk;
            s2sh = 0.f;
        }
        if (tid < GG) f1[tid] = 0.f;
        __syncthreads();
        if (skip) { __syncthreads(); continue; }

        float myS2 = 0.f;
        for (int idx = tid; idx < T_ITER * GG * NN; idx += 1024) {
            if (d_lab[idx] == key) {
                int g = (idx >> 12) & (GG - 1);
                int n = idx & (NN - 1);
                float w = nw[(size_t)g * NN + n];
                atomicAdd(&f1[g], w);
                myS2 += w * w;
            }
        }
        if (myS2 != 0.f) atomicAdd(&s2sh, myS2);
        __syncthreads();

        bool i0 = false; int n0 = 0;
        u32 hi = (u32)(key >> 32), m = hi >> 1;
        if (!(hi & 1u) && (m - 1u) < (u32)NN && (u32)key == key0_lo((int)(m - 1u))) {
            i0 = true; n0 = (int)(m - 1u);
        }
        for (int pair = tid; pair < GG * GG; pair += 1024) {
            int a = pair >> 6, b = pair & (GG - 1);
            float f0a = i0 ? nw[(size_t)a * NN + n0] : 0.f;
            float f0b = i0 ? nw[(size_t)b * NN + n0] : 0.f;
            float fa = f0a + f1[a], fb = f0b + f1[b];
            float corr = fa * fb - f0a * f0b;     // remove GEMM double count
            if (a == b) corr -= s2sh;             // remove diag double count
            if (corr != 0.f) d_K[pair] += corr;   // only this block touches d_K
        }
        __syncthreads();
    }

    // normalize
    __shared__ float rsd[GG];
    if (tid < GG) rsd[tid] = rsqrtf(d_K[tid * GG + tid]);
    __syncthreads();
    for (int i = tid; i < GG * GG; i += 1024) {
        int g = i >> 6, h = i & (GG - 1);
        out[i] = d_K[i] * rsd[g] * rsd[h];
    }
}

extern "C" void kernel_launch(void* const* d_in, const int* in_sizes, int n_in,
                              void* d_out, int out_size) {
    const int* nbr;
    const float* nw;
    if (in_sizes[0] == GG * NN * DD) {
        nbr = (const int*)d_in[0];
        nw  = (const float*)d_in[1];
    } else {
        nbr = (const int*)d_in[1];
        nw  = (const float*)d_in[0];
    }
    float* out = (float*)d_out;

    prepK   <<<GG + 256, 512>>> (nw);     // 64 gram blocks + 256 zero blocks
    wlK     <<<GG * CLU, TPB>>> (nbr);
    fixnormK<<<1, 1024>>> (nw, out);
}

// round 4
// speedup vs baseline: 5.5644x; 1.6367x over previous
#include <cuda_runtime.h>
#include <stdint.h>

// WL graph kernel v4 — v3 with the gram bank-conflict fixed (no smem,
// warp-per-4-rows coalesced global reads).
// G=64, N=4096, D=16, T=4.
//
// K = W W^T (diag x5)  [iter-0 bins + singleton later bins]
//   + exact corrections for any key with >=2 later instances or a kept
//     iter-0 label (self-reported via hash-table CAS to an overflow list,
//     fixed exactly in K3; expected empty for this data).

typedef unsigned long long u64;
typedef unsigned int u32;

#define GG 64
#define NN 4096
#define DD 16
#define T_ITER 4
#define CLU 4
#define TPB 512
#define NPC (NN / CLU)
#define TBITS 21
#define TSIZE (1u << TBITS)
#define TMASK (TSIZE - 1u)
#define OVF_CAP 4096

// ---- static device scratch ----
__device__ u64   d_key[TSIZE];               // 16 MB hash table (0 = empty)
__device__ u64   d_lab[T_ITER * GG * NN];    //  8 MB labels (fixup scan)
__device__ u64   d_ovf[OVF_CAP];
__device__ u32   d_ovf_cnt;
__device__ float d_K[GG * GG];

// ---- hashing ----
__device__ __forceinline__ u32 fmix32(u32 h) {
    h ^= h >> 16; h *= 0x85ebca6bu;
    h ^= h >> 13; h *= 0xc2b2ae35u;
    h ^= h >> 16; return h;
}
__device__ __forceinline__ u32 key0_lo(int n) { return fmix32((u32)n) & ~1u; }
__device__ __forceinline__ u32 key0_hi(int n) { return (u32)(n + 1) << 1; }

// ---- cluster helpers ----
__device__ __forceinline__ u32 smem_u32(const void* p) {
    return (u32)__cvta_generic_to_shared(p);
}
__device__ __forceinline__ u32 mapa_sh(u32 a, u32 r) {
    u32 o; asm("mapa.shared::cluster.u32 %0, %1, %2;" : "=r"(o) : "r"(a), "r"(r));
    return o;
}
__device__ __forceinline__ void st_sh_cluster(u32 a, u32 v) {
    asm volatile("st.shared::cluster.u32 [%0], %1;" :: "r"(a), "r"(v) : "memory");
}
__device__ __forceinline__ u32 ctarank() {
    u32 r; asm("mov.u32 %0, %%cluster_ctarank;" : "=r"(r)); return r;
}
__device__ __forceinline__ void cluster_sync_() {
    asm volatile("barrier.cluster.arrive.aligned;" ::: "memory");
    asm volatile("barrier.cluster.wait.aligned;" ::: "memory");
}

// ---- side effects: record label; self-report dups / kept iter-0 labels ----
__device__ __forceinline__ void sideFx(u64 lab, int g, int t, int n) {
    d_lab[(((size_t)(t - 1) * GG + g) << 12) + n] = lab;
    u32 hi = (u32)(lab >> 32);
    u32 m = hi >> 1;
    if (!(hi & 1u) && (m - 1u) < (u32)NN && (u32)lab == key0_lo((int)(m - 1u))) {
        u32 id = atomicAdd(&d_ovf_cnt, 1u);
        if (id < OVF_CAP) d_ovf[id] = lab;
        return;
    }
    u32 slot = ((u32)lab >> 1) & TMASK;
    for (;;) {
        u64 prev = atomicCAS(reinterpret_cast<unsigned long long*>(&d_key[slot]),
                             0ULL, (unsigned long long)lab);
        if (prev == 0ULL) break;
        if (prev == lab) {
            u32 id = atomicAdd(&d_ovf_cnt, 1u);
            if (id < OVF_CAP) d_ovf[id] = lab;
            break;
        }
        slot = (slot + 1u) & TMASK;
    }
}

// ---- K1: fused table-zero + gram (K = W W^T, diag x5) ----
// Gram blocks: one per g-row; warp w computes h = w, w+16, w+32, w+48.
// Lanes read consecutive float4s (coalesced, conflict-free, no smem).
__global__ void __launch_bounds__(512) prepK(const float* __restrict__ nw) {
    const int tid = threadIdx.x;
    if (blockIdx.x >= GG) {
        // zero blocks: 256 blocks cover 16 MB of d_key as ulonglong2
        const int zb = blockIdx.x - GG;
        ulonglong2* p = reinterpret_cast<ulonglong2*>(d_key);
        const int base = zb * (512 * 8);
        #pragma unroll
        for (int k = 0; k < 8; k++)
            p[base + k * 512 + tid] = make_ulonglong2(0ULL, 0ULL);
        if (zb == 0 && tid == 0) d_ovf_cnt = 0u;
        return;
    }
    const int g = blockIdx.x;
    const int warp = tid >> 5, lane = tid & 31;
    const float4* rowg = reinterpret_cast<const float4*>(nw + (size_t)g * NN);
    #pragma unroll
    for (int hh = 0; hh < 4; hh++) {
        const int h = warp + hh * 16;
        const float4* rowh = reinterpret_cast<const float4*>(nw + (size_t)h * NN);
        float acc = 0.f;
        #pragma unroll 8
        for (int j = 0; j < 32; j++) {
            float4 a = rowg[lane + j * 32];
            float4 b = rowh[lane + j * 32];
            acc += a.x * b.x + a.y * b.y + a.z * b.z + a.w * b.w;
        }
        acc += __shfl_xor_sync(0xffffffffu, acc, 16);
        acc += __shfl_xor_sync(0xffffffffu, acc, 8);
        acc += __shfl_xor_sync(0xffffffffu, acc, 4);
        acc += __shfl_xor_sync(0xffffffffu, acc, 2);
        acc += __shfl_xor_sync(0xffffffffu, acc, 1);
        if (lane == 0) d_K[g * GG + h] = (g == h) ? acc * 5.0f : acc;
    }
}

// ---- K2: 4 WL iterations; 4-CTA cluster per graph, 2 nodes/thread ----
__global__ void __launch_bounds__(TPB, 2) __cluster_dims__(CLU, 1, 1)
wlK(const int* __restrict__ nbr) {
    __shared__ u32 buf[2][NN];                  // double-buffered full copy, 32 KB
    const int tid = threadIdx.x;
    const u32 rank = ctarank();
    const int g = blockIdx.x / CLU;

    const int n0 = (int)rank * NPC + tid;
    const int n1 = n0 + TPB;

    // hoist neighbor lists into registers (iteration-invariant)
    const int4* p0 = reinterpret_cast<const int4*>(nbr + ((size_t)g * NN + n0) * DD);
    const int4* p1 = reinterpret_cast<const int4*>(nbr + ((size_t)g * NN + n1) * DD);
    int4 A0 = p0[0], A1 = p0[1], A2 = p0[2], A3 = p0[3];
    int4 B0 = p1[0], B1 = p1[1], B2 = p1[2], B3 = p1[3];

    // init buffer 0 (own full replicated copy)
    #pragma unroll
    for (int i = tid; i < NN; i += TPB) buf[0][i] = key0_lo(i);

    u32 lo0 = key0_lo(n0), hi0 = key0_hi(n0);
    u32 lo1 = key0_lo(n1), hi1 = key0_hi(n1);

    const u32 myaddr = smem_u32(&buf[0][0]);
    const u32 pa0 = mapa_sh(myaddr, 0), pa1 = mapa_sh(myaddr, 1);
    const u32 pa2 = mapa_sh(myaddr, 2), pa3 = mapa_sh(myaddr, 3);

    __syncthreads();
    cluster_sync_();   // all CTAs resident + buf[0] initialized everywhere

    const u64 PHI = 0x9E3779B97F4A7C15ULL;
    const u64 M1  = 0xff51afd7ed558ccdULL;
    #pragma unroll 1
    for (int t = 1; t <= T_ITER; t++) {
        const u32* cur = buf[(t - 1) & 1];
        const u32 nxtoff = (u32)((t & 1) * (NN * 4));
        const u64 salt = (u64)t * 0xD6E8FEB86659FD93ULL;

        u32 s0 = cur[A0.x] + cur[A0.y] + cur[A0.z] + cur[A0.w]
               + cur[A1.x] + cur[A1.y] + cur[A1.z] + cur[A1.w]
               + cur[A2.x] + cur[A2.y] + cur[A2.z] + cur[A2.w]
               + cur[A3.x] + cur[A3.y] + cur[A3.z] + cur[A3.w];
        u32 s1 = cur[B0.x] + cur[B0.y] + cur[B0.z] + cur[B0.w]
               + cur[B1.x] + cur[B1.y] + cur[B1.z] + cur[B1.w]
               + cur[B2.x] + cur[B2.y] + cur[B2.z] + cur[B2.w]
               + cur[B3.x] + cur[B3.y] + cur[B3.z] + cur[B3.w];

        u64 own0 = ((u64)hi0 << 32) | lo0;
        u64 own1 = ((u64)hi1 << 32) | lo1;
        u64 h0 = (own0 + salt + (u64)s0 * PHI) * M1;  h0 ^= h0 >> 32;
        u64 h1 = (own1 + salt + (u64)s1 * PHI) * M1;  h1 ^= h1 >> 32;
        u64 lab0 = (s0 == lo0 * 16u) ? own0 : ((h0 | 2ULL) & ~1ULL);
        u64 lab1 = (s1 == lo1 * 16u) ? own1 : ((h1 | 2ULL) & ~1ULL);

        // global side effects (off the smem critical path)
        sideFx(lab0, g, t, n0);
        sideFx(lab1, g, t, n1);

        // publish new labels to all 4 replicated copies
        u32 nl0 = (u32)lab0, nl1 = (u32)lab1;
        u32 o0 = nxtoff + (u32)n0 * 4u, o1 = nxtoff + (u32)n1 * 4u;
        st_sh_cluster(pa0 + o0, nl0);  st_sh_cluster(pa0 + o1, nl1);
        st_sh_cluster(pa1 + o0, nl0);  st_sh_cluster(pa1 + o1, nl1);
        st_sh_cluster(pa2 + o0, nl0);  st_sh_cluster(pa2 + o1, nl1);
        st_sh_cluster(pa3 + o0, nl0);  st_sh_cluster(pa3 + o1, nl1);
        lo0 = nl0; hi0 = (u32)(lab0 >> 32);
        lo1 = nl1; hi1 = (u32)(lab1 >> 32);

        cluster_sync_();   // writes visible cluster-wide before next reads
    }
}

// ---- K3: single-block exact fixups (expected none) + normalize ----
__global__ void __launch_bounds__(1024) fixnormK(const float* __restrict__ nw,
                                                 float* __restrict__ out) {
    const int tid = threadIdx.x;
    __shared__ float f1[GG];
    __shared__ float s2sh;
    __shared__ int skip;

    u32 M = d_ovf_cnt; if (M > OVF_CAP) M = OVF_CAP;
    for (u32 i = 0; i < M; i++) {
        u64 key = d_ovf[i];
        if (tid == 0) {
            int sk = 0;
            for (u32 j = 0; j < i; j++) if (d_ovf[j] == key) { sk = 1; break; }
            skip = sk;
            s2sh = 0.f;
        }
        if (tid < GG) f1[tid] = 0.f;
        __syncthreads();
        if (skip) { __syncthreads(); continue; }

        float myS2 = 0.f;
        for (int idx = tid; idx < T_ITER * GG * NN; idx += 1024) {
            if (d_lab[idx] == key) {
                int g = (idx >> 12) & (GG - 1);
                int n = idx & (NN - 1);
                float w = nw[(size_t)g * NN + n];
                atomicAdd(&f1[g], w);
                myS2 += w * w;
            }
        }
        if (myS2 != 0.f) atomicAdd(&s2sh, myS2);
        __syncthreads();

        bool i0 = false; int n0 = 0;
        u32 hi = (u32)(key >> 32), m = hi >> 1;
        if (!(hi & 1u) && (m - 1u) < (u32)NN && (u32)key == key0_lo((int)(m - 1u))) {
            i0 = true; n0 = (int)(m - 1u);
        }
        for (int pair = tid; pair < GG * GG; pair += 1024) {
            int a = pair >> 6, b = pair & (GG - 1);
            float f0a = i0 ? nw[(size_t)a * NN + n0] : 0.f;
            float f0b = i0 ? nw[(size_t)b * NN + n0] : 0.f;
            float fa = f0a + f1[a], fb = f0b + f1[b];
            float corr = fa * fb - f0a * f0b;     // remove GEMM double count
            if (a == b) corr -= s2sh;             // remove diag double count
            if (corr != 0.f) d_K[pair] += corr;   // only this block touches d_K
        }
        __syncthreads();
    }

    // normalize
    __shared__ float rsd[GG];
    if (tid < GG) rsd[tid] = rsqrtf(d_K[tid * GG + tid]);
    __syncthreads();
    for (int i = tid; i < GG * GG; i += 1024) {
        int g = i >> 6, h = i & (GG - 1);
        out[i] = d_K[i] * rsd[g] * rsd[h];
    }
}

extern "C" void kernel_launch(void* const* d_in, const int* in_sizes, int n_in,
                              void* d_out, int out_size) {
    const int* nbr;
    const float* nw;
    if (in_sizes[0] == GG * NN * DD) {
        nbr = (const int*)d_in[0];
        nw  = (const float*)d_in[1];
    } else {
        nbr = (const int*)d_in[1];
        nw  = (const float*)d_in[0];
    }
    float* out = (float*)d_out;

    prepK   <<<GG + 256, 512>>> (nw);     // 64 gram blocks + 256 zero blocks
    wlK     <<<GG * CLU, TPB>>> (nbr);
    fixnormK<<<1, 1024>>> (nw, out);
}

// round 6
// speedup vs baseline: 5.8807x; 1.0568x over previous
#include <cuda_runtime.h>
#include <stdint.h>

// WL graph kernel v6 — v5 with two fixes:
//  (1) zero the FULL 8 MB key table (replay staleness caused spurious dups)
//  (2) per-graph s2 in the fixup (scalar s2 wrongly hit all diagonal entries)
// G=64, N=4096, D=16, T=4.

typedef unsigned long long u64;
typedef unsigned int u32;

#define GG 64
#define NN 4096
#define DD 16
#define T_ITER 4
#define CLU 4
#define TPB 512
#define NPC (NN / CLU)
#define TBITS 21
#define TSIZE (1u << TBITS)
#define TMASK (TSIZE - 1u)
#define OVF_CAP 4096

// ---- static device scratch ----
__device__ u32   d_key[TSIZE];               // 8 MB compressed-key table (0=empty)
__device__ u64   d_lab[T_ITER * GG * NN];    // 8 MB labels (fixup scan)
__device__ u64   d_ovf[OVF_CAP];
__device__ u32   d_ovf_cnt;
__device__ float d_Kpart[4][GG * GG];        // gram partials per N-chunk

// ---- hashing ----
__device__ __forceinline__ u32 fmix32(u32 h) {
    h ^= h >> 16; h *= 0x85ebca6bu;
    h ^= h >> 13; h *= 0xc2b2ae35u;
    h ^= h >> 16; return h;
}
__device__ __forceinline__ u32 key0_lo(int n) { return fmix32((u32)n) & ~1u; }
__device__ __forceinline__ u32 key0_hi(int n) { return (u32)(n + 1) << 1; }

// ---- cluster helpers ----
__device__ __forceinline__ u32 smem_u32(const void* p) {
    return (u32)__cvta_generic_to_shared(p);
}
__device__ __forceinline__ u32 mapa_sh(u32 a, u32 r) {
    u32 o; asm("mapa.shared::cluster.u32 %0, %1, %2;" : "=r"(o) : "r"(a), "r"(r));
    return o;
}
__device__ __forceinline__ void st_sh_cluster64(u32 a, u64 v) {
    asm volatile("st.shared::cluster.u64 [%0], %1;" :: "r"(a), "l"(v) : "memory");
}
__device__ __forceinline__ u32 ctarank() {
    u32 r; asm("mov.u32 %0, %%cluster_ctarank;" : "=r"(r)); return r;
}
__device__ __forceinline__ void cluster_sync_() {
    asm volatile("barrier.cluster.arrive.aligned;" ::: "memory");
    asm volatile("barrier.cluster.wait.aligned;" ::: "memory");
}

// ---- side effects: record label; self-report dups / kept iter-0 labels ----
// 32-bit compressed key: deterministic, so true duplicates are ALWAYS caught.
// False dups cause spurious singleton reports whose exact correction is zero.
__device__ __forceinline__ void sideFx(u64 lab, int g, int t, int n) {
    d_lab[(((size_t)(t - 1) * GG + g) << 12) + n] = lab;
    u32 lo = (u32)lab, hi = (u32)(lab >> 32);
    u32 m = hi >> 1;
    if (!(hi & 1u) && (m - 1u) < (u32)NN && lo == key0_lo((int)(m - 1u))) {
        u32 id = atomicAdd(&d_ovf_cnt, 1u);
        if (id < OVF_CAP) d_ovf[id] = lab;
        return;
    }
    u32 slot = (lo >> 1) & TMASK;
    u32 ck = (hi ^ (lo * 0x9E3779B9u)) | 1u;    // never 0
    for (;;) {
        u32 prev = atomicCAS(&d_key[slot], 0u, ck);
        if (prev == 0u) break;
        if (prev == ck) {
            u32 id = atomicAdd(&d_ovf_cnt, 1u);
            if (id < OVF_CAP) d_ovf[id] = lab;
            break;
        }
        slot = (slot + 1u) & TMASK;
    }
}

// ---- K1: fused table-zero + chunked gram partials ----
// blocks [0,256): gram (g = b>>2, chunk c = b&3 over 1024 floats)
// blocks [256,384): zero the FULL 8 MB of d_key (8 x 16B per thread)
__global__ void __launch_bounds__(512) prepK(const float* __restrict__ nw) {
    const int tid = threadIdx.x;
    const int b = blockIdx.x;
    if (b >= 256) {
        const int zb = b - 256;                      // 128 zero blocks
        ulonglong2* p = reinterpret_cast<ulonglong2*>(d_key);
        const int base = zb * (512 * 8);             // 8 x 16B per thread
        #pragma unroll
        for (int k = 0; k < 8; k++)
            p[base + k * 512 + tid] = make_ulonglong2(0ULL, 0ULL);
        if (zb == 0 && tid == 0) d_ovf_cnt = 0u;
        return;
    }
    const int g = b >> 2, c = b & 3;
    const int warp = tid >> 5, lane = tid & 31;
    const float4* base4 = reinterpret_cast<const float4*>(nw);
    const int off = c * 256 + lane;                  // chunk of 256 float4
    float4 rg[8];
    #pragma unroll
    for (int j = 0; j < 8; j++) rg[j] = base4[(size_t)g * 1024 + off + j * 32];
    float acc[4];
    #pragma unroll
    for (int k = 0; k < 4; k++) {
        const int h = warp * 4 + k;
        const float4* rh = base4 + (size_t)h * 1024;
        float a = 0.f;
        #pragma unroll
        for (int j = 0; j < 8; j++) {
            float4 bb = rh[off + j * 32];
            a += rg[j].x * bb.x + rg[j].y * bb.y + rg[j].z * bb.z + rg[j].w * bb.w;
        }
        acc[k] = a;
    }
    #pragma unroll
    for (int k = 0; k < 4; k++) {
        #pragma unroll
        for (int s = 16; s; s >>= 1)
            acc[k] += __shfl_xor_sync(0xffffffffu, acc[k], s);
    }
    if (lane == 0) {
        const int h = warp * 4;
        float* dst = &d_Kpart[c][g * GG + h];
        dst[0] = acc[0]; dst[1] = acc[1]; dst[2] = acc[2]; dst[3] = acc[3];
    }
}

// ---- K2: 4 WL iterations; 4-CTA cluster per graph, 2 adjacent nodes/thread ----
__global__ void __launch_bounds__(TPB, 2) __cluster_dims__(CLU, 1, 1)
wlK(const int* __restrict__ nbr) {
    __shared__ u32 buf[2][NN];                  // double-buffered full copy, 32 KB
    const int tid = threadIdx.x;
    const u32 rank = ctarank();
    const int g = blockIdx.x / CLU;

    const int n0 = (int)rank * NPC + tid * 2;   // two adjacent nodes
    const int n1 = n0 + 1;

    // hoist both neighbor lists (128 contiguous bytes) into registers
    const int4* p = reinterpret_cast<const int4*>(nbr + ((size_t)g * NN + n0) * DD);
    int4 A0 = p[0], A1 = p[1], A2 = p[2], A3 = p[3];
    int4 B0 = p[4], B1 = p[5], B2 = p[6], B3 = p[7];

    #pragma unroll
    for (int i = tid; i < NN; i += TPB) buf[0][i] = key0_lo(i);

    u32 lo0 = key0_lo(n0), hi0 = key0_hi(n0);
    u32 lo1 = key0_lo(n1), hi1 = key0_hi(n1);

    const u32 myaddr = smem_u32(&buf[0][0]);
    const u32 pa0 = mapa_sh(myaddr, 0), pa1 = mapa_sh(myaddr, 1);
    const u32 pa2 = mapa_sh(myaddr, 2), pa3 = mapa_sh(myaddr, 3);

    __syncthreads();    // local buf[0] ready; t=1 reads are local-only.
                        // Peers' buf[1] is untouched until after the t=1 sync,
                        // so no initial cluster sync is needed.

    const u64 PHI = 0x9E3779B97F4A7C15ULL;
    const u64 M1  = 0xff51afd7ed558ccdULL;
    #pragma unroll 1
    for (int t = 1; t <= T_ITER; t++) {
        const u32* cur = buf[(t - 1) & 1];
        const u64 salt = (u64)t * 0xD6E8FEB86659FD93ULL;

        u32 s0 = cur[A0.x] + cur[A0.y] + cur[A0.z] + cur[A0.w]
               + cur[A1.x] + cur[A1.y] + cur[A1.z] + cur[A1.w]
               + cur[A2.x] + cur[A2.y] + cur[A2.z] + cur[A2.w]
               + cur[A3.x] + cur[A3.y] + cur[A3.z] + cur[A3.w];
        u32 s1 = cur[B0.x] + cur[B0.y] + cur[B0.z] + cur[B0.w]
               + cur[B1.x] + cur[B1.y] + cur[B1.z] + cur[B1.w]
               + cur[B2.x] + cur[B2.y] + cur[B2.z] + cur[B2.w]
               + cur[B3.x] + cur[B3.y] + cur[B3.z] + cur[B3.w];

        u64 own0 = ((u64)hi0 << 32) | lo0;
        u64 own1 = ((u64)hi1 << 32) | lo1;
        u64 h0 = (own0 + salt + (u64)s0 * PHI) * M1;  h0 ^= h0 >> 32;
        u64 h1 = (own1 + salt + (u64)s1 * PHI) * M1;  h1 ^= h1 >> 32;
        u64 lab0 = (s0 == lo0 * 16u) ? own0 : ((h0 | 2ULL) & ~1ULL);
        u64 lab1 = (s1 == lo1 * 16u) ? own1 : ((h1 | 2ULL) & ~1ULL);

        sideFx(lab0, g, t, n0);
        sideFx(lab1, g, t, n1);

        lo0 = (u32)lab0; hi0 = (u32)(lab0 >> 32);
        lo1 = (u32)lab1; hi1 = (u32)(lab1 >> 32);

        if (t < T_ITER) {   // last iteration's labels are never read back
            const u32 nxtoff = (u32)((t & 1) * (NN * 4));
            u64 pk = ((u64)lo1 << 32) | lo0;        // two adjacent u32 labels
            u32 o = nxtoff + (u32)n0 * 4u;          // 8B-aligned (n0 even)
            st_sh_cluster64(pa0 + o, pk);
            st_sh_cluster64(pa1 + o, pk);
            st_sh_cluster64(pa2 + o, pk);
            st_sh_cluster64(pa3 + o, pk);
            cluster_sync_();
        }
    }
}

// ---- K3: sum gram partials + exact fixups (expected none) + normalize ----
__global__ void __launch_bounds__(1024) fixnormK(const float* __restrict__ nw,
                                                 float* __restrict__ out) {
    const int tid = threadIdx.x;
    __shared__ float Ksh[GG * GG];
    __shared__ float f1[GG];
    __shared__ float s2g[GG];          // per-graph sum of w^2 for this key
    __shared__ int skip;

    for (int i = tid; i < GG * GG; i += 1024) {
        float v = d_Kpart[0][i] + d_Kpart[1][i] + d_Kpart[2][i] + d_Kpart[3][i];
        int g = i >> 6, h = i & (GG - 1);
        Ksh[i] = (g == h) ? v * 5.0f : v;   // +4*sum(w^2) singleton diag term
    }
    __syncthreads();

    u32 M = d_ovf_cnt; if (M > OVF_CAP) M = OVF_CAP;
    for (u32 i = 0; i < M; i++) {
        u64 key = d_ovf[i];
        if (tid == 0) {
            int sk = 0;
            for (u32 j = 0; j < i; j++) if (d_ovf[j] == key) { sk = 1; break; }
            skip = sk;
        }
        if (tid < GG) { f1[tid] = 0.f; s2g[tid] = 0.f; }
        __syncthreads();
        if (skip) { __syncthreads(); continue; }

        for (int idx = tid; idx < T_ITER * GG * NN; idx += 1024) {
            if (d_lab[idx] == key) {
                int g = (idx >> 12) & (GG - 1);
                int n = idx & (NN - 1);
                float w = nw[(size_t)g * NN + n];
                atomicAdd(&f1[g], w);
                atomicAdd(&s2g[g], w * w);
            }
        }
        __syncthreads();

        bool i0 = false; int n0 = 0;
        u32 hi = (u32)(key >> 32), m = hi >> 1;
        if (!(hi & 1u) && (m - 1u) < (u32)NN && (u32)key == key0_lo((int)(m - 1u))) {
            i0 = true; n0 = (int)(m - 1u);
        }
        for (int pair = tid; pair < GG * GG; pair += 1024) {
            int a = pair >> 6, b2 = pair & (GG - 1);
            float f0a = i0 ? nw[(size_t)a * NN + n0] : 0.f;
            float f0b = i0 ? nw[(size_t)b2 * NN + n0] : 0.f;
            float fa = f0a + f1[a], fb = f0b + f1[b2];
            float corr = fa * fb - f0a * f0b;    // remove GEMM double count
            if (a == b2) corr -= s2g[a];         // remove diag singleton count
            Ksh[pair] += corr;
        }
        __syncthreads();
    }

    __shared__ float rsd[GG];
    if (tid < GG) rsd[tid] = rsqrtf(Ksh[tid * GG + tid]);
    __syncthreads();
    for (int i = tid; i < GG * GG; i += 1024) {
        int g = i >> 6, h = i & (GG - 1);
        out[i] = Ksh[i] * rsd[g] * rsd[h];
    }
}

extern "C" void kernel_launch(void* const* d_in, const int* in_sizes, int n_in,
                              void* d_out, int out_size) {
    const int* nbr;
    const float* nw;
    if (in_sizes[0] == GG * NN * DD) {
        nbr = (const int*)d_in[0];
        nw  = (const float*)d_in[1];
    } else {
        nbr = (const int*)d_in[1];
        nw  = (const float*)d_in[0];
    }
    float* out = (float*)d_out;

    prepK   <<<384, 512>>> (nw);      // 256 gram-chunk blocks + 128 zero blocks
    wlK     <<<GG * CLU, TPB>>> (nbr);
    fixnormK<<<1, 1024>>> (nw, out);
}